// round 2
// baseline (speedup 1.0000x reference)
#include <cuda_runtime.h>

// Composed affine map: 9 rows, each padded to 12 floats: [w0..w8, bias, 0, 0]
__device__ float g_aff[9 * 12];

// ---------------------------------------------------------------------------
// Kernel 1: compose the 8 conv layers into one affine map (A, v).
// ---------------------------------------------------------------------------
__global__ void compose_kernel(const float* __restrict__ w,   // [8*9]
                               const float* __restrict__ b) { // [8]
    __shared__ float M[2][9][10];
    int t = threadIdx.x;
    int o = t / 10;   // output element index (i*3+j)
    int c = t % 10;   // column (0..8 = input elem, 9 = bias)

    if (t < 90) M[0][o][c] = (c < 9 && o == c) ? 1.0f : 0.0f;
    __syncthreads();

    int cur = 0;
    for (int d = 0; d < 8; d++) {
        float acc = 0.0f;
        if (t < 90) {
            int i = o / 3, j = o % 3;
#pragma unroll
            for (int di = -1; di <= 1; di++) {
#pragma unroll
                for (int dj = -1; dj <= 1; dj++) {
                    int ii = i + di, jj = j + dj;
                    if (ii >= 0 && ii < 3 && jj >= 0 && jj < 3) {
                        acc += w[d * 9 + (di + 1) * 3 + (dj + 1)] *
                               M[cur][ii * 3 + jj][c];
                    }
                }
            }
            if (c == 9) acc += b[d];
            M[1 ^ cur][o][c] = acc;
        }
        __syncthreads();
        cur ^= 1;
    }

    if (t < 90) g_aff[o * 12 + c] = M[cur][o][c];
    if (t >= 90 && t < 108) {
        int p = t - 90;
        g_aff[(p / 2) * 12 + 10 + (p % 2)] = 0.0f;
    }
}

// ---------------------------------------------------------------------------
// Kernel 2: smem-staged streaming y = A x + v.
// Block = 256 threads, 1024 rows (9216 floats = 36864 B staged in smem).
//   stage-in : 9 coalesced LDG.128 -> STS.128 per thread
//   compute  : thread t owns rows {t, t+256, t+512, t+768}; scalar LDS at
//              word-stride 9 (coprime with 32 banks -> conflict-free);
//              results overwrite the same smem row in place.
//   stage-out: 9 LDS.128 -> coalesced STG.128 per thread
// ---------------------------------------------------------------------------
#define TPB 256
#define ROWS_PER_BLOCK 1024
#define FLOATS_PER_BLOCK (ROWS_PER_BLOCK * 9)

__global__ __launch_bounds__(TPB, 4)
void affine_kernel(const float* __restrict__ x,
                   float* __restrict__ out,
                   int nrows) {
    __shared__ float sA[9 * 12];
    __shared__ float sx[FLOATS_PER_BLOCK];

    int t = threadIdx.x;
    int r0 = blockIdx.x * ROWS_PER_BLOCK;
    int rows_here = nrows - r0;
    if (rows_here > ROWS_PER_BLOCK) rows_here = ROWS_PER_BLOCK;
    int cnt = rows_here * 9;  // floats this block handles

    if (t < 108) sA[t] = g_aff[t];

    const float* xg = x + (long long)r0 * 9;
    float*       og = out + (long long)r0 * 9;

    // ---- stage in (coalesced) ----
#pragma unroll
    for (int k = 0; k < 9; k++) {
        int fi = (k * TPB + t) * 4;
        if (fi + 4 <= cnt) {
            *(float4*)&sx[fi] = *(const float4*)&xg[fi];
        } else if (fi < cnt) {
            for (int u = fi; u < cnt; u++) sx[u] = xg[u];
        }
    }
    __syncthreads();

    // ---- compute: 2 rows per pass, 2 passes ----
#pragma unroll
    for (int h = 0; h < 2; h++) {
        int ra = t + (2 * h) * TPB;       // local row a
        int rb = t + (2 * h + 1) * TPB;   // local row b
        bool va = (r0 + ra) < nrows;
        bool vb = (r0 + rb) < nrows;

        float xa[9], xb[9];
        if (va) {
#pragma unroll
            for (int j = 0; j < 9; j++) xa[j] = sx[ra * 9 + j];
        }
        if (vb) {
#pragma unroll
            for (int j = 0; j < 9; j++) xb[j] = sx[rb * 9 + j];
        }

#pragma unroll
        for (int o = 0; o < 9; o++) {
            float4 a0 = *(const float4*)&sA[o * 12 + 0];
            float4 a1 = *(const float4*)&sA[o * 12 + 4];
            float4 a2 = *(const float4*)&sA[o * 12 + 8]; // x = w8, y = bias

            if (va) {
                float acc = fmaf(a0.x, xa[0], a2.y);
                acc = fmaf(a0.y, xa[1], acc);
                acc = fmaf(a0.z, xa[2], acc);
                acc = fmaf(a0.w, xa[3], acc);
                acc = fmaf(a1.x, xa[4], acc);
                acc = fmaf(a1.y, xa[5], acc);
                acc = fmaf(a1.z, xa[6], acc);
                acc = fmaf(a1.w, xa[7], acc);
                acc = fmaf(a2.x, xa[8], acc);
                sx[ra * 9 + o] = acc;  // safe: xa already in registers
            }
            if (vb) {
                float acc = fmaf(a0.x, xb[0], a2.y);
                acc = fmaf(a0.y, xb[1], acc);
                acc = fmaf(a0.z, xb[2], acc);
                acc = fmaf(a0.w, xb[3], acc);
                acc = fmaf(a1.x, xb[4], acc);
                acc = fmaf(a1.y, xb[5], acc);
                acc = fmaf(a1.z, xb[6], acc);
                acc = fmaf(a1.w, xb[7], acc);
                acc = fmaf(a2.x, xb[8], acc);
                sx[rb * 9 + o] = acc;
            }
        }
    }
    __syncthreads();

    // ---- stage out (coalesced) ----
#pragma unroll
    for (int k = 0; k < 9; k++) {
        int fi = (k * TPB + t) * 4;
        if (fi + 4 <= cnt) {
            *(float4*)&og[fi] = *(const float4*)&sx[fi];
        } else if (fi < cnt) {
            for (int u = fi; u < cnt; u++) og[u] = sx[u];
        }
    }
}

extern "C" void kernel_launch(void* const* d_in, const int* in_sizes, int n_in,
                              void* d_out, int out_size) {
    const float* x = (const float*)d_in[0];  // [N*9]
    const float* w = (const float*)d_in[1];  // [8*9]
    const float* b = (const float*)d_in[2];  // [8]
    float* out = (float*)d_out;              // [N*9]

    int nrows = in_sizes[0] / 9;

    compose_kernel<<<1, 96>>>(w, b);

    int blocks = (nrows + ROWS_PER_BLOCK - 1) / ROWS_PER_BLOCK;
    affine_kernel<<<blocks, TPB>>>(x, out, nrows);
}

// round 3
// speedup vs baseline: 1.5028x; 1.5028x over previous
#include <cuda_runtime.h>

// Composed affine map: 9 rows, each padded to 12 floats: [w0..w8, bias, 0, 0]
__device__ float g_aff[9 * 12];

// ---------------------------------------------------------------------------
// Kernel 1: compose the 8 conv layers into one affine map (A, v).
// ---------------------------------------------------------------------------
__global__ void compose_kernel(const float* __restrict__ w,   // [8*9]
                               const float* __restrict__ b) { // [8]
    __shared__ float M[2][9][10];
    int t = threadIdx.x;
    int o = t / 10;
    int c = t % 10;

    if (t < 90) M[0][o][c] = (c < 9 && o == c) ? 1.0f : 0.0f;
    __syncthreads();

    int cur = 0;
    for (int d = 0; d < 8; d++) {
        float acc = 0.0f;
        if (t < 90) {
            int i = o / 3, j = o % 3;
#pragma unroll
            for (int di = -1; di <= 1; di++) {
#pragma unroll
                for (int dj = -1; dj <= 1; dj++) {
                    int ii = i + di, jj = j + dj;
                    if (ii >= 0 && ii < 3 && jj >= 0 && jj < 3) {
                        acc += w[d * 9 + (di + 1) * 3 + (dj + 1)] *
                               M[cur][ii * 3 + jj][c];
                    }
                }
            }
            if (c == 9) acc += b[d];
            M[1 ^ cur][o][c] = acc;
        }
        __syncthreads();
        cur ^= 1;
    }

    if (t < 90) g_aff[o * 12 + c] = M[cur][o][c];
    if (t >= 90 && t < 108) {
        int p = t - 90;
        g_aff[(p / 2) * 12 + 10 + (p % 2)] = 0.0f;
    }
}

// ---------------------------------------------------------------------------
// Kernel 2: vector-only smem-transposed streaming y = A x + v.
//   stage-in : coalesced LDG.128 -> STS.128 (contiguous, 4 wf/instr)
//   compute  : thread t vector-loads its OWN 144 B chunk (4 rows) with 9x
//              LDS.128 at stride 144 B -> conflict-free (banks (4t+4k+w)%32
//              cover all 32 banks per 8-lane phase), computes 4 rows fully
//              in registers, vector-stores y back over the same chunk.
//   stage-out: coalesced LDS.128 -> STG.128
// No scalar shared ops on the hot path; 2 barriers per tile.
// ---------------------------------------------------------------------------
#define TPB 256
#define RPT 4
#define ROWS_PER_BLOCK (TPB * RPT)          // 1024 rows
#define WORDS_PER_BLOCK (ROWS_PER_BLOCK * 9) // 9216 floats = 36864 B

__global__ __launch_bounds__(TPB, 2)
void affine_kernel(const float* __restrict__ x,
                   float* __restrict__ out,
                   int nrows) {
    __shared__ __align__(16) float sA[9 * 12];
    __shared__ __align__(16) float sx[WORDS_PER_BLOCK];

    int t = threadIdx.x;
    long long r0 = (long long)blockIdx.x * ROWS_PER_BLOCK;
    int rows_here = (int)(((long long)nrows - r0) < ROWS_PER_BLOCK
                              ? (nrows - r0) : ROWS_PER_BLOCK);
    int cnt = rows_here * 9;

    if (t < 108) sA[t] = g_aff[t];

    const float* xg = x + r0 * 9;
    float*       og = out + r0 * 9;

    // ---- stage in (fully coalesced) ----
#pragma unroll
    for (int k = 0; k < 9; k++) {
        int fi = (k * TPB + t) * 4;
        if (fi + 4 <= cnt) {
            *(float4*)&sx[fi] = *(const float4*)&xg[fi];
        } else if (fi < cnt) {
            for (int u = fi; u < cnt; u++) sx[u] = xg[u];
        }
    }
    __syncthreads();

    if (rows_here == ROWS_PER_BLOCK) {
        // ---- fast path: all-vector private-chunk compute ----
        float xr[36];
        float4* xv = (float4*)xr;
#pragma unroll
        for (int k = 0; k < 9; k++)
            xv[k] = *(const float4*)&sx[t * 36 + 4 * k];

        float y[36];
#pragma unroll
        for (int o = 0; o < 9; o++) {
            float4 a0 = *(const float4*)&sA[o * 12 + 0];
            float4 a1 = *(const float4*)&sA[o * 12 + 4];
            float4 a2 = *(const float4*)&sA[o * 12 + 8]; // x=w8, y=bias
#pragma unroll
            for (int r = 0; r < 4; r++) {
                const float* xp = xr + r * 9;
                float acc = fmaf(a0.x, xp[0], a2.y);
                acc = fmaf(a0.y, xp[1], acc);
                acc = fmaf(a0.z, xp[2], acc);
                acc = fmaf(a0.w, xp[3], acc);
                acc = fmaf(a1.x, xp[4], acc);
                acc = fmaf(a1.y, xp[5], acc);
                acc = fmaf(a1.z, xp[6], acc);
                acc = fmaf(a1.w, xp[7], acc);
                acc = fmaf(a2.x, xp[8], acc);
                y[r * 9 + o] = acc;
            }
        }

        const float4* yv = (const float4*)y;
#pragma unroll
        for (int k = 0; k < 9; k++)
            *(float4*)&sx[t * 36 + 4 * k] = yv[k];
    } else {
        // ---- tail block (at most one per grid): scalar per-row ----
        int lr0 = t * RPT;
        for (int lr = lr0; lr < lr0 + RPT && lr < rows_here; lr++) {
            float xp[9];
#pragma unroll
            for (int c = 0; c < 9; c++) xp[c] = sx[lr * 9 + c];
#pragma unroll
            for (int o = 0; o < 9; o++) {
                float acc = sA[o * 12 + 9];
#pragma unroll
                for (int c = 0; c < 9; c++)
                    acc = fmaf(sA[o * 12 + c], xp[c], acc);
                sx[lr * 9 + o] = acc;
            }
        }
    }
    __syncthreads();

    // ---- stage out (fully coalesced) ----
#pragma unroll
    for (int k = 0; k < 9; k++) {
        int fi = (k * TPB + t) * 4;
        if (fi + 4 <= cnt) {
            *(float4*)&og[fi] = *(const float4*)&sx[fi];
        } else if (fi < cnt) {
            for (int u = fi; u < cnt; u++) og[u] = sx[u];
        }
    }
}

extern "C" void kernel_launch(void* const* d_in, const int* in_sizes, int n_in,
                              void* d_out, int out_size) {
    const float* x = (const float*)d_in[0];  // [N*9]
    const float* w = (const float*)d_in[1];  // [8*9]
    const float* b = (const float*)d_in[2];  // [8]
    float* out = (float*)d_out;              // [N*9]

    int nrows = in_sizes[0] / 9;

    compose_kernel<<<1, 96>>>(w, b);

    int blocks = (nrows + ROWS_PER_BLOCK - 1) / ROWS_PER_BLOCK;
    affine_kernel<<<blocks, TPB>>>(x, out, nrows);
}